// round 5
// baseline (speedup 1.0000x reference)
#include <cuda_runtime.h>
#include <cuda_pipeline.h>
#include <cstdint>

// LIF scan, cp.async in-pipeline + cp.async.bulk out-pipeline.
//   out[b,0,h] = 0
//   for k=1..T-1: reset=(V>1); V = 0.9V + z[b,k-1,h] - reset; out[b,k,h] = (V>1)
//
// Block = 128 threads <-> 128 h-chains; grid = 128 blocks (1/SM).
// Input staged through an 8-deep x 16-step cp.async pipeline (8KB/stage).
// Spikes written with cheap STS into a double-buffered 8KB tile, drained by
// cp.async.bulk (async shared->global, 512B row per issuing thread), so the
// single warp per SMSP spends its issue slots on the recurrence, not on STG.

#define Bb    32
#define T     1024
#define Hh    512
#define BETA  0.9f
#define THR   1.0f

#define HT      128            // h per block
#define SROWS   16             // t-steps per stage
#define NSTAGE  8              // input pipeline depth (64 KB)
#define NSTEP   (T - 1)        // 1023 valid steps
#define NST     (T / SROWS)    // 64 stages; last stage has 15 valid steps

__device__ __forceinline__ uint32_t smem_u32(const void* p) {
    return (uint32_t)__cvta_generic_to_shared(p);
}

__global__ __launch_bounds__(HT, 1)
void lif_kernel(const float* __restrict__ z, float* __restrict__ out) {
    __shared__ float sbuf[NSTAGE][SROWS][HT];   // 64 KB input stages
    __shared__ float sspk[2][SROWS][HT];        // 16 KB spike out tiles

    const int tid = threadIdx.x;
    const int b   = blockIdx.x >> 2;
    const int h0  = (blockIdx.x & 3) * HT;

    const float* zb = z + (size_t)b * T * Hh + h0;
    float* const ob = out + (size_t)b * T * Hh + h0;

    // loader mapping: thread -> row tid/8, 64B chunk (tid%8)*16 floats
    const int lr = tid >> 3;
    const int lc = (tid & 7) * 16;

    // k = 0 output row is zero (d_out poisoned).
    ob[tid] = 0.0f;

    // ── prologue: fill stages 0..NSTAGE-2 ────────────────────────────────
    #pragma unroll
    for (int s = 0; s < NSTAGE - 1; ++s) {
        const float* src = zb + (size_t)(s * SROWS + lr) * Hh + lc;
        float* dst = &sbuf[s][lr][lc];
        __pipeline_memcpy_async(dst,      src,      16);
        __pipeline_memcpy_async(dst + 4,  src + 4,  16);
        __pipeline_memcpy_async(dst + 8,  src + 8,  16);
        __pipeline_memcpy_async(dst + 12, src + 12, 16);
        __pipeline_commit();
    }

    float V = 0.0f;
    bool  p = false;   // spike/reset predicate, carried across steps

    for (int s = 0; s < NST; ++s) {
        __pipeline_wait_prior(NSTAGE - 2);   // input stage s resident

        // out-slot s&1 reused from stage s-2: its bulk copy must be done
        if (tid < SROWS && s >= 2)
            asm volatile("cp.async.bulk.wait_group.read 1;" ::: "memory");
        __syncthreads();

        // refill input stage s + NSTAGE-1 (empty commit at tail keeps the
        // wait_prior group arithmetic uniform)
        const int sn = s + NSTAGE - 1;
        if (sn < NST) {
            const float* src = zb + (size_t)(sn * SROWS + lr) * Hh + lc;
            float* dst = &sbuf[sn & (NSTAGE - 1)][lr][lc];
            __pipeline_memcpy_async(dst,      src,      16);
            __pipeline_memcpy_async(dst + 4,  src + 4,  16);
            __pipeline_memcpy_async(dst + 8,  src + 8,  16);
            __pipeline_memcpy_async(dst + 12, src + 12, 16);
        }
        __pipeline_commit();

        const float* sin  = &sbuf[s & (NSTAGE - 1)][0][tid];
        float*       sout = &sspk[s & 1][0][tid];

        if (s < NST - 1) {
            #pragma unroll
            for (int r = 0; r < SROWS; ++r) {
                float zin = sin[r * HT];
                float inj = p ? (zin - THR) : zin;   // z - reset*thr
                V = fmaf(BETA, V, inj);
                p = V > THR;                          // spike == next reset
                sout[r * HT] = p ? 1.0f : 0.0f;
            }
        } else {
            #pragma unroll
            for (int r = 0; r < SROWS - 1; ++r) {    // j=1008..1022 only
                float zin = sin[r * HT];
                float inj = p ? (zin - THR) : zin;
                V = fmaf(BETA, V, inj);
                p = V > THR;
                sout[r * HT] = p ? 1.0f : 0.0f;
            }
        }
        __syncthreads();   // spike tile complete

        // drain spike tile: one 512B row per issuing thread, async
        if (tid < SROWS) {
            const int k = s * SROWS + tid + 1;       // output row
            if (k < T) {
                asm volatile("fence.proxy.async.shared::cta;" ::: "memory");
                uint32_t saddr = smem_u32(&sspk[s & 1][tid][0]);
                float* gdst = ob + (size_t)k * Hh;
                asm volatile(
                    "cp.async.bulk.global.shared::cta.bulk_group [%0], [%1], %2;"
                    :: "l"(gdst), "r"(saddr), "r"((int)(HT * 4)) : "memory");
            }
            asm volatile("cp.async.bulk.commit_group;" ::: "memory");
        }
    }

    // flush outstanding bulk stores before exit
    if (tid < SROWS)
        asm volatile("cp.async.bulk.wait_group.read 0;" ::: "memory");
}

extern "C" void kernel_launch(void* const* d_in, const int* in_sizes, int n_in,
                              void* d_out, int out_size) {
    const float* z = (const float*)d_in[0];
    float* out = (float*)d_out;
    lif_kernel<<<(Bb * Hh) / HT, HT>>>(z, out);
}

// round 6
// speedup vs baseline: 2.3231x; 2.3231x over previous
#include <cuda_runtime.h>
#include <cuda_pipeline.h>

// LIF scan — barrier-free per-thread cp.async pipeline.
//   out[b,0,h] = 0
//   for k=1..T-1: reset=(V>1); V = 0.9V + z[b,k-1,h] - reset; out[b,k,h] = (V>1)
//
// 1 thread <-> 1 (b,h) chain; 128 blocks x 128 threads (1 CTA/SM).
// Each thread cp.asyncs ONLY its own 4B/row into smem, waits on its OWN
// commit groups, and reads back its own column -> no __syncthreads anywhere.
// 15 stages x 8 rows x 4B = 480B in flight per thread (60KB/SM) hides DRAM.
// reset == previous spike, so the step body is 4 flops, bit-identical to the
// reference grouping: tmp = z - s (s in {0,1}); V = fmaf(0.9, V, tmp).

#define Bb    32
#define T     1024
#define Hh    512
#define BETA  0.9f
#define THR   1.0f

#define HT      128            // h per block
#define SROWS   8              // t-steps per stage
#define NSTAGE  16             // pipeline depth (64 KB smem)
#define NST     (T / SROWS)    // 128 stages; last stage: 7 valid steps

__global__ __launch_bounds__(HT, 1)
void lif_kernel(const float* __restrict__ z, float* __restrict__ out) {
    __shared__ float sbuf[NSTAGE][SROWS][HT];   // 64 KB

    const int tid = threadIdx.x;
    const int b   = blockIdx.x >> 2;
    const int h0  = (blockIdx.x & 3) * HT;

    const float* zp = z   + (size_t)b * T * Hh + h0 + tid;  // own column
    float*       op = out + (size_t)b * T * Hh + h0 + tid;

    // k = 0 output is zero (d_out poisoned).
    op[0] = 0.0f;

    // ── prologue: fill 15 stages, 4B per row, own column only ────────────
    #pragma unroll
    for (int s = 0; s < NSTAGE - 1; ++s) {
        #pragma unroll
        for (int r = 0; r < SROWS; ++r)
            __pipeline_memcpy_async(&sbuf[s][r][tid],
                                    zp + (size_t)(s * SROWS + r) * Hh, 4);
        __pipeline_commit();
    }

    float V  = 0.0f;
    float sf = 0.0f;   // spike (== next step's reset), in {0,1}

    for (int st = 0; st < NST; ++st) {
        __pipeline_wait_prior(NSTAGE - 2);   // my stage st is resident

        // refill stage st+15 into the slot freed at stage st-1
        const int sn = st + NSTAGE - 1;
        if (sn < NST) {
            float* dst = &sbuf[sn & (NSTAGE - 1)][0][tid];
            const float* src = zp + (size_t)sn * SROWS * Hh;
            #pragma unroll
            for (int r = 0; r < SROWS; ++r)
                __pipeline_memcpy_async(dst + r * HT, src + (size_t)r * Hh, 4);
        }
        __pipeline_commit();                 // always: keeps group count uniform

        const float* sp  = &sbuf[st & (NSTAGE - 1)][0][tid];
        float*       opk = op + (size_t)(st * SROWS + 1) * Hh;

        if (st < NST - 1) {
            #pragma unroll
            for (int r = 0; r < SROWS; ++r) {
                float zin = sp[r * HT];
                float tmp = zin - sf;             // z - reset (bit-exact)
                V = fmaf(BETA, V, tmp);
                sf = (V > THR) ? 1.0f : 0.0f;     // spike == next reset
                opk[(size_t)r * Hh] = sf;
            }
        } else {
            #pragma unroll
            for (int r = 0; r < SROWS - 1; ++r) { // steps 1016..1022
                float zin = sp[r * HT];
                float tmp = zin - sf;
                V = fmaf(BETA, V, tmp);
                sf = (V > THR) ? 1.0f : 0.0f;
                opk[(size_t)r * Hh] = sf;
            }
        }
    }
}

extern "C" void kernel_launch(void* const* d_in, const int* in_sizes, int n_in,
                              void* d_out, int out_size) {
    const float* z = (const float*)d_in[0];
    float* out = (float*)d_out;
    lif_kernel<<<(Bb * Hh) / HT, HT>>>(z, out);
}